// round 5
// baseline (speedup 1.0000x reference)
#include <cuda_runtime.h>
#include <math.h>

#define D_MODEL 2048
#define NUM_HEADS 16
#define HEAD_DIM 128
#define MAX_SEQ_LEN 32768
#define KB 64                       // key-blocks per head (splits per head)
#define CHUNK (MAX_SEQ_LEN / KB)    // 512 keys per block
#define HALF (CHUNK / 2)            // 256 keys per stream
#define SCALE 0.08838834764831845f  // 1/sqrt(128)

// ---------------- device scratch (no allocations allowed) ----------------
__device__ float g_q[D_MODEL];
__device__ float g_k[D_MODEL];
__device__ float g_v[D_MODEL];
__device__ float g_attn[D_MODEL];
__device__ float g_pm[NUM_HEADS * KB];
__device__ float g_pl[NUM_HEADS * KB];
__device__ float g_pacc[NUM_HEADS * KB * HEAD_DIM];
__device__ unsigned g_sem[NUM_HEADS];   // zero-initialized; reset by reducer

// ---------------- K1: fused QKV matvecs (WARP per output row) -------------
// 6144 rows, 8 rows per 256-thread block -> 768 blocks (0.65 wave).
// Each thread: 16 float4 loads in 4 pipelined batches.
__global__ __launch_bounds__(256) void qkv_kernel(const float* __restrict__ x,
                                                  const float* __restrict__ Wq,
                                                  const float* __restrict__ Wk,
                                                  const float* __restrict__ Wv) {
    __shared__ float xs[D_MODEL];
    int tid = threadIdx.x;
    {
        float4* xs4 = (float4*)xs;
        const float4* x4 = (const float4*)x;
#pragma unroll
        for (int i = 0; i < 2; i++) xs4[tid + i * 256] = x4[tid + i * 256];
    }
    if (blockIdx.x == 0 && tid < NUM_HEADS) g_sem[tid] = 0;   // safety reset
    __syncthreads();

    int grow = blockIdx.x * 8 + (tid >> 5);   // 0..6143 global row
    int lane = tid & 31;
    int mat  = grow >> 11;                    // 0=Wq 1=Wk 2=Wv
    int row  = grow & 2047;
    const float* W = (mat == 0) ? Wq : ((mat == 1) ? Wk : Wv);
    const float4* wr = (const float4*)(W + (size_t)row * D_MODEL);

    float acc = 0.f;
#pragma unroll
    for (int b = 0; b < 4; b++) {
        float4 w[4];
#pragma unroll
        for (int i = 0; i < 4; i++) w[i] = __ldcs(wr + lane + (b * 4 + i) * 32);
#pragma unroll
        for (int i = 0; i < 4; i++) {
            int j = lane + (b * 4 + i) * 32;
            acc += xs[j * 4 + 0] * w[i].x + xs[j * 4 + 1] * w[i].y
                 + xs[j * 4 + 2] * w[i].z + xs[j * 4 + 3] * w[i].w;
        }
    }
#pragma unroll
    for (int o = 16; o; o >>= 1) acc += __shfl_xor_sync(0xffffffffu, acc, o);

    if (lane == 0) {
        float* dst = (mat == 0) ? g_q : ((mat == 1) ? g_k : g_v);
        dst[row] = acc;
    }
}

// ---------------- K2: FUSED cache copy + flash attention + final reduce ---
// grid = NUM_HEADS * KB = 1024 blocks of 256 threads => single wave.
// Last-finishing block of each head combines all its split partials.
__global__ __launch_bounds__(256) void fused_copy_attn_kernel(
        const float4* __restrict__ pk,
        const float4* __restrict__ pv,
        float4* __restrict__ ok,
        float4* __restrict__ ov,
        const int* __restrict__ ci_p) {
    int h  = blockIdx.x / KB;
    int kb = blockIdx.x % KB;
    int ci = *ci_p;
    int kstart = kb * CHUNK;

    __shared__ float wm[8], wl[8];
    __shared__ float wacc[8][HEAD_DIM];
    __shared__ bool is_last;

    int tid = threadIdx.x, wid = tid >> 5, lane = tid & 31;

    float4 q     = ((const float4*)(g_q + h * HEAD_DIM))[lane];
    float4 foldk = ((const float4*)(g_k + h * HEAD_DIM))[lane];
    float4 foldv = ((const float4*)(g_v + h * HEAD_DIM))[lane];

    float m = -INFINITY, l = 0.f;
    float4 acc = make_float4(0.f, 0.f, 0.f, 0.f);

    const int seg_stride = NUM_HEADS * (HEAD_DIM / 4);   // 512 float4 per key row
    const int hbase = h * (HEAD_DIM / 4) + lane;

    for (int it = 0; it < HALF / 8; it++) {
        int keyA = kstart + wid + it * 8;
        int keyB = keyA + HALF;
        size_t ia = (size_t)keyA * seg_stride + hbase;
        size_t ib = (size_t)keyB * seg_stride + hbase;

        float4 kA, vA, kB, vB;
        if (keyA == ci) { kA = foldk; vA = foldv; }
        else            { kA = __ldcs(pk + ia); vA = __ldcs(pv + ia); }
        if (keyB == ci) { kB = foldk; vB = foldv; }
        else            { kB = __ldcs(pk + ib); vB = __ldcs(pv + ib); }
        __stcs(ok + ia, kA); __stcs(ov + ia, vA);
        __stcs(ok + ib, kB); __stcs(ov + ib, vB);

        bool aval = keyA < ci;
        bool bval = keyB < ci;
        if (aval || bval) {
            float sA = kA.x * q.x + kA.y * q.y + kA.z * q.z + kA.w * q.w;
            float sB = kB.x * q.x + kB.y * q.y + kB.z * q.z + kB.w * q.w;
#pragma unroll
            for (int o = 16; o; o >>= 1) {
                sA += __shfl_xor_sync(0xffffffffu, sA, o);
                sB += __shfl_xor_sync(0xffffffffu, sB, o);
            }
            sA = aval ? sA * SCALE : -INFINITY;
            sB = bval ? sB * SCALE : -INFINITY;
            float mn   = fmaxf(m, fmaxf(sA, sB));
            float corr = __expf(m - mn);
            float pA   = __expf(sA - mn);
            float pB   = __expf(sB - mn);
            acc.x = acc.x * corr + pA * vA.x + pB * vB.x;
            acc.y = acc.y * corr + pA * vA.y + pB * vB.y;
            acc.z = acc.z * corr + pA * vA.z + pB * vB.z;
            acc.w = acc.w * corr + pA * vA.w + pB * vB.w;
            l = l * corr + pA + pB;
            m = mn;
        }
    }

    wacc[wid][lane * 4 + 0] = acc.x;
    wacc[wid][lane * 4 + 1] = acc.y;
    wacc[wid][lane * 4 + 2] = acc.z;
    wacc[wid][lane * 4 + 3] = acc.w;
    if (lane == 0) { wm[wid] = m; wl[wid] = l; }
    __syncthreads();

    if (tid < HEAD_DIM) {
        float mb = -INFINITY;
#pragma unroll
        for (int w = 0; w < 8; w++) mb = fmaxf(mb, wm[w]);
        float lb = 0.f, od = 0.f;
        if (mb != -INFINITY) {
#pragma unroll
            for (int w = 0; w < 8; w++) {
                float e = __expf(wm[w] - mb);
                lb += wl[w] * e;
                od += wacc[w][tid] * e;
            }
        }
        int idx = h * KB + kb;
        g_pacc[idx * HEAD_DIM + tid] = od;
        if (tid == 0) { g_pm[idx] = mb; g_pl[idx] = lb; }
    }
    __syncthreads();

    // ---- last-block-done: the 64th finisher of this head reduces it ----
    if (tid == 0) {
        __threadfence();                       // publish partials
        unsigned old = atomicAdd(&g_sem[h], 1u);
        is_last = (old == KB - 1);
        if (is_last) g_sem[h] = 0;             // reset for graph replay
    }
    __syncthreads();
    if (!is_last) return;
    __threadfence();                           // acquire others' partials

    float* red = wacc[0];                      // reuse smem
    if (tid < HEAD_DIM) {
        float qv = g_q[h * HEAD_DIM + tid];
        float kv = g_k[h * HEAD_DIM + tid];
        red[tid] = qv * kv;
    }
    __syncthreads();
    for (int s = 64; s; s >>= 1) {
        if (tid < s) red[tid] += red[tid + s];
        __syncthreads();
    }
    float s_new = red[0] * SCALE;              // new key is always valid

    if (tid < HEAD_DIM) {
        float mg = s_new;
#pragma unroll 8
        for (int sp = 0; sp < KB; sp++) mg = fmaxf(mg, g_pm[h * KB + sp]);

        float en  = __expf(s_new - mg);
        float num = en * g_v[h * HEAD_DIM + tid];
        float den = en;
#pragma unroll 8
        for (int sp = 0; sp < KB; sp++) {
            float e = __expf(g_pm[h * KB + sp] - mg);
            num += e * g_pacc[(h * KB + sp) * HEAD_DIM + tid];
            den += e * g_pl[h * KB + sp];
        }
        g_attn[h * HEAD_DIM + tid] = num / den;
    }
}

// ---------------- K3: output projection y = attn @ Wo.T ------------------
// 128 threads per row, 2 rows per 256-block -> grid 1024 (one full wave).
__global__ __launch_bounds__(256) void proj_kernel(const float* __restrict__ Wo,
                                                   float* __restrict__ y) {
    __shared__ float xs[D_MODEL];
    __shared__ float part[8];
    int tid = threadIdx.x;
    {
        float4* xs4 = (float4*)xs;
        const float4* a4 = (const float4*)g_attn;
#pragma unroll
        for (int i = 0; i < 2; i++) xs4[tid + i * 256] = a4[tid + i * 256];
    }
    __syncthreads();

    int sub  = tid & 127;                    // thread within row group
    int lane = tid & 31;
    int row  = blockIdx.x * 2 + (tid >> 7);
    const float4* wr = (const float4*)(Wo + (size_t)row * D_MODEL);

    float4 w[4];
#pragma unroll
    for (int it = 0; it < 4; it++) w[it] = __ldcs(wr + sub + it * 128);
    float acc = 0.f;
#pragma unroll
    for (int it = 0; it < 4; it++) {
        int j = sub + it * 128;
        acc += xs[j * 4 + 0] * w[it].x + xs[j * 4 + 1] * w[it].y
             + xs[j * 4 + 2] * w[it].z + xs[j * 4 + 3] * w[it].w;
    }
#pragma unroll
    for (int o = 16; o; o >>= 1) acc += __shfl_xor_sync(0xffffffffu, acc, o);
    if (lane == 0) part[tid >> 5] = acc;
    __syncthreads();
    if (sub == 0) {
        int p = (tid >> 5);                  // 0 or 4
        y[row] = part[p] + part[p + 1] + part[p + 2] + part[p + 3];
    }
}

// ---------------- launch ---------------------------------------------------
extern "C" void kernel_launch(void* const* d_in, const int* in_sizes, int n_in,
                              void* d_out, int out_size) {
    const float* x  = (const float*)d_in[0];
    const float* Wq = (const float*)d_in[1];
    const float* Wk = (const float*)d_in[2];
    const float* Wv = (const float*)d_in[3];
    const float* Wo = (const float*)d_in[4];
    const float* pk = (const float*)d_in[5];
    const float* pv = (const float*)d_in[6];
    const int*   ci = (const int*)d_in[7];

    float* y  = (float*)d_out;
    float* ok = y + D_MODEL;
    float* ov = ok + (size_t)MAX_SEQ_LEN * D_MODEL;

    qkv_kernel<<<768, 256>>>(x, Wq, Wk, Wv);
    fused_copy_attn_kernel<<<NUM_HEADS * KB, 256>>>(
        (const float4*)pk, (const float4*)pv,
        (float4*)ok, (float4*)ov, ci);
    proj_kernel<<<1024, 256>>>(Wo, y);
}